// round 13
// baseline (speedup 1.0000x reference)
#include <cuda_runtime.h>
#include <math.h>

#define FULLM 0xffffffffu

// Static scratch (no allocations)
__device__ float2 g_PL[1024000];     // [bid=b*16+p][row] -> {Pv=(dis*xy*th)^2 raw, l1}
__device__ float4 g_psum[8192];      // [bid][tile] -> {sum d2, sum dxy2, sum t2, sum liou}
__device__ float4 g_v01e[64000];     // [b][row] -> {v0, v1, exp(v0), exp(v1)}
__device__ float  g_Zp[64][8][2];    // partial sums of exp(v0), exp(v1)
__device__ float  g_res[3072];       // [1024][3]
__device__ unsigned g_done = 0;      // completion counter (reset each replay)

// ---------------------------------------------------------------------------
// Kernel 1: per-row stats vs priors + per-tile prior sums.
// grid (64 batches, 8 tiles of 125 rows, 2 prior-halves) x 256 thr.
// Block layout: 2 groups of 4 priors x 128 row-slots.
// ---------------------------------------------------------------------------
__global__ __launch_bounds__(256, 7) void k_stats(const float* __restrict__ OUT,
                                                  const float* __restrict__ LAB)
{
    const int b = blockIdx.x, tile = blockIdx.y, z = blockIdx.z;
    const int tid = threadIdx.x;
    const int pg  = tid >> 7;          // 0: local priors 0-3, 1: local priors 4-7
    const int rl  = tid & 127;
    const int w = tid >> 5, lane = tid & 31;

    __shared__ float sPr[624];         // 8 priors (this z-half) x 78
    __shared__ float sE[8];
    __shared__ float sW[8][16];        // per-warp partials [warp][j*4+c]
    for (int j = tid; j < 624; j += 256)
        sPr[j] = LAB[(long long)b * 1248 + z * 624 + j];
    __syncthreads();

    const int row = tile * 125 + rl;
    const bool act = (rl < 125);
    float e0 = 0.0f, e1 = 0.0f;
    float acc[4];
    float2 v23, v45;

    const float* R = OUT + (long long)b * 78000 + row * 78;
    const float* P0 = sPr + pg * 4 * 78;

    if (act) {
        float2 v01 = *reinterpret_cast<const float2*>(R);
        v23 = *reinterpret_cast<const float2*>(R + 2);
        v45 = *reinterpret_cast<const float2*>(R + 4);
        if (z == 0 && pg == 0) {
            e0 = expf(v01.x);
            e1 = expf(v01.y);
            g_v01e[b * 1000 + row] = make_float4(v01.x, v01.y, e0, e1);
        }
        #pragma unroll
        for (int j = 0; j < 4; j++) acc[j] = 0.0f;
        #pragma unroll 4
        for (int c = 6; c < 78; c += 2) {
            float2 v = *reinterpret_cast<const float2*>(R + c);
            #pragma unroll
            for (int j = 0; j < 4; j++) {
                float2 pv = *reinterpret_cast<const float2*>(P0 + j * 78 + c);
                acc[j] += fabsf(v.x - pv.x) + fabsf(v.y - pv.y);
            }
        }
    }

    // per-prior: compute {Pv, l1}, accumulate tile sums {d2, dxy2, t2, liou}
    #pragma unroll
    for (int j = 0; j < 4; j++) {
        float d2 = 0.0f, dxy2 = 0.0f, t2 = 0.0f, li = 0.0f;
        if (act) {
            const float* Pj = P0 + j * 78;
            float dx = v23.y - Pj[3];
            float dy = v45.x - Pj[4];
            dxy2 = dx * dx + dy * dy;
            float th = v45.y - Pj[5];
            t2 = th * th;
            float l1 = acc[j];
            float dis = l1 * (1.0f / 72.0f);
            d2 = dis * dis;
            // liou = 2*l1/(2160+l1): poly approx of 1/(1+u), u = l1/2160 (k-sum only)
            float u = l1 * (1.0f / 2160.0f);
            li = 2.0f * l1 * (1.0f / 2160.0f) * (1.0f - u * (1.0f - u * (1.0f - u)));
            g_PL[(long long)(b * 16 + z * 8 + pg * 4 + j) * 1000 + row] =
                make_float2(d2 * dxy2 * t2, l1);
        }
        for (int o = 16; o; o >>= 1) {
            d2   += __shfl_xor_sync(FULLM, d2,   o);
            dxy2 += __shfl_xor_sync(FULLM, dxy2, o);
            t2   += __shfl_xor_sync(FULLM, t2,   o);
            li   += __shfl_xor_sync(FULLM, li,   o);
        }
        if (lane == 0) {
            sW[w][j*4+0] = d2; sW[w][j*4+1] = dxy2;
            sW[w][j*4+2] = t2; sW[w][j*4+3] = li;
        }
    }

    if (z == 0 && pg == 0) {
        for (int o = 16; o; o >>= 1) {
            e0 += __shfl_xor_sync(FULLM, e0, o);
            e1 += __shfl_xor_sync(FULLM, e1, o);
        }
        if (lane == 0) { sE[w] = e0; sE[w + 4] = e1; }
    }
    __syncthreads();

    if (tid < 32) {
        int lp = tid >> 2, c = tid & 3, j = lp & 3;
        int wb = (lp >= 4) ? 4 : 0;
        float s = sW[wb][j*4+c] + sW[wb+1][j*4+c] + sW[wb+2][j*4+c] + sW[wb+3][j*4+c];
        int bid2 = b * 16 + z * 8 + lp;
        ((float*)g_psum)[(bid2 * 8 + tile) * 4 + c] = s;
    }
    if (z == 0 && tid == 0) {
        g_Zp[b][tile][0] = sE[0] + sE[1] + sE[2] + sE[3];
        g_Zp[b][tile][1] = sE[4] + sE[5] + sE[6] + sE[7];
    }
}

// ---------------------------------------------------------------------------
// Kernel 2: per-(batch,lane) cost keys, 4-pass radix top-k set selection,
// masked tails, folded final reduce. grid = 1024 blocks, 256 threads.
// ---------------------------------------------------------------------------
__global__ __launch_bounds__(256, 7) void k_sel(const float* __restrict__ OUT,
                                                const float* __restrict__ LAB,
                                                float* __restrict__ out)
{
    const int bid = blockIdx.x;
    const int b = bid >> 4;
    const float* F  = OUT + (long long)b * 78000;
    const float* PR = LAB + (long long)bid * 78;

    __shared__ unsigned sKey[1000];
    __shared__ int      sHist[2][256];
    __shared__ float    sRed[48];
    __shared__ float    sB[12];        // 0:cscale 1:lnZ0 2:iZ0 3:lnZ1 4:iZ1 5..: norms
    __shared__ int      sKk;
    __shared__ unsigned sPfxS;
    __shared__ int      sKkS, sCLS, sCES;
    __shared__ bool     sLast;

    const int tid = threadIdx.x, w = tid >> 5, lane = tid & 31;

    // phase 0: warp-parallel preliminaries (Z, cscale, k, hist zero) — 1 barrier
    if (w == 0) {
        float z = 0.0f;
        if (lane < 8)       z = g_Zp[b][lane][0];
        else if (lane < 16) z = g_Zp[b][lane - 8][1];
        z += __shfl_xor_sync(FULLM, z, 4);
        z += __shfl_xor_sync(FULLM, z, 2);
        z += __shfl_xor_sync(FULLM, z, 1);
        if (lane == 0) { sB[1] = logf(z); sB[2] = 1.0f / z; }
        if (lane == 8) { sB[3] = logf(z); sB[4] = 1.0f / z; }
    } else if (w == 1) {
        float4 p4 = make_float4(0.0f, 0.0f, 0.0f, 0.0f);
        if (lane < 8) p4 = g_psum[bid * 8 + lane];
        #pragma unroll
        for (int o = 4; o; o >>= 1) {
            p4.x += __shfl_xor_sync(FULLM, p4.x, o);
            p4.y += __shfl_xor_sync(FULLM, p4.y, o);
            p4.z += __shfl_xor_sync(FULLM, p4.z, o);
            p4.w += __shfl_xor_sync(FULLM, p4.w, o);
        }
        if (lane == 0) {
            float nd = fmaxf(sqrtf(p4.x), 1e-12f);
            float nx = fmaxf(sqrtf(p4.y), 1e-12f);
            float nt = fmaxf(sqrtf(p4.z), 1e-12f);
            float den = nd * nx * nt;
            sB[0] = 3.0f / (den * den);        // W_SIM / (Nd*Nxy*Nth)^2
            int k = (int)p4.w;
            if (k < 1) k = 1;
            if (k > 64) k = 64;
            sKk = k;
            sPfxS = 0u; sCLS = 0; sKkS = k; sCES = 0;
        }
    } else {
        for (int j = tid - 64; j < 512; j += 192) ((int*)sHist)[j] = 0;
    }
    __syncthreads();

    const float cscale = sB[0];
    const float lnZ0 = sB[1], iZ0 = sB[2], lnZ1 = sB[3], iZ1 = sB[4];
    const int   k = sKk;
    const float pr0 = PR[0], pr1 = PR[1];
    const int nr = (tid < 232) ? 4 : 3;     // 232*4 + 24*3 = 1000

    // phase 1: compute final order-preserving keys directly
    unsigned kr[4];
    #pragma unroll
    for (int rr = 0; rr < 4; rr++) {
        kr[rr] = 0xFFFFFFFFu;
        if (rr < nr) {
            int i = tid + rr * 256;
            float2 st = g_PL[(long long)bid * 1000 + i];
            float4 ve = g_v01e[b * 1000 + i];
            float s0 = ve.z * iZ0, s1 = ve.w * iZ1;
            float a0 = (1.0f - s0); a0 = a0 * a0 * (ve.x - lnZ0);
            float a1 = (1.0f - s1); a1 = a1 * a1 * (ve.y - lnZ1);
            float cost = cscale * st.x + a0 * pr0 + a1 * pr1;   // W_CLS = 1
            unsigned u = __float_as_uint(cost);
            u = (u & 0x80000000u) ? ~u : (u | 0x80000000u);
            kr[rr] = u;
            sKey[i] = u;
        }
    }

    // 4-pass radix select (MSB first): exact k-th smallest key + CL/CE
    #pragma unroll
    for (int p = 0; p < 4; p++) {
        const int shift = 24 - 8 * p;
        const int buf = p & 1;
        const unsigned pfx = sPfxS;
        #pragma unroll
        for (int rr = 0; rr < 4; rr++) {
            if (rr < nr) {
                bool match = (p == 0) || (((kr[rr] ^ pfx) >> (shift + 8)) == 0u);
                if (match) atomicAdd(&sHist[buf][(kr[rr] >> shift) & 255u], 1);
            }
        }
        __syncthreads();
        if (w == 0) {
            int hv[8]; int local = 0;
            #pragma unroll
            for (int j = 0; j < 8; j++) { hv[j] = sHist[buf][lane * 8 + j]; local += hv[j]; }
            int inc = local;
            #pragma unroll
            for (int o = 1; o < 32; o <<= 1) {
                int t = __shfl_up_sync(FULLM, inc, o);
                if (lane >= o) inc += t;
            }
            const int cumb = inc - local;
            const int kk = sKkS;
            unsigned ball = __ballot_sync(FULLM, inc >= kk);
            int sel_lane = __ffs(ball) - 1;
            if (lane == sel_lane) {
                int run = cumb;
                #pragma unroll
                for (int j = 0; j < 8; j++) {
                    int h = hv[j];
                    if (run + h >= kk) {
                        sPfxS = pfx | ((unsigned)(lane * 8 + j) << shift);
                        sKkS  = kk - run;
                        sCLS += run;
                        sCES  = h;
                        break;
                    }
                    run += h;
                }
            }
        } else {
            for (int j = tid - 32; j < 256; j += 224) sHist[buf ^ 1][j] = 0;
        }
        __syncthreads();
    }
    const unsigned Tkey = sPfxS;
    const int CL = sCLS, CE = sCES;
    const int  m    = k - CL;
    const bool easy = (CE == m);

    // pass A: select + accumulate col sums, focal, liou over selected rows
    const int tgt = (pr0 >= pr1) ? 0 : 1;
    float sq0=0, sq1=0, sq2=0, sq3=0, sfl=0, sll=0;
    int selMask = 0;
    #pragma unroll
    for (int rr = 0; rr < 4; rr++) {
        if (rr >= nr) continue;
        int i = tid + rr * 256;
        bool s;
        if (kr[rr] < Tkey) s = true;
        else if (kr[rr] == Tkey) {
            if (easy) s = true;
            else {
                int rank = 0;
                for (int j = 0; j < i; j++) rank += (sKey[j] == Tkey) ? 1 : 0;
                s = (rank < m);
            }
        } else s = false;
        if (s) {
            selMask |= (1 << rr);
            const float* R = F + i * 78;
            float2 v23 = *reinterpret_cast<const float2*>(R + 2);
            float2 v45 = *reinterpret_cast<const float2*>(R + 4);
            sq0 += v23.x * v23.x;  sq1 += v23.y * v23.y;
            sq2 += v45.x * v45.x;  sq3 += v45.y * v45.y;
            float4 ve = g_v01e[b * 1000 + i];
            float at = (tgt == 0) ? ve.x : ve.y;
            float ao = (tgt == 0) ? ve.y : ve.x;
            float e  = expf(ao - at);
            float lp = -log1pf(e);
            float pt = expf(lp);
            float om = 1.0f - pt;
            sfl += -om * om * lp;
            float l1 = g_PL[(long long)bid * 1000 + i].y;
            sll += 1.0f - __fdividef(2160.0f - l1, 2160.0f + l1 + 1e-9f);
        }
    }
    for (int o = 16; o; o >>= 1) {
        sq0 += __shfl_xor_sync(FULLM, sq0, o);
        sq1 += __shfl_xor_sync(FULLM, sq1, o);
        sq2 += __shfl_xor_sync(FULLM, sq2, o);
        sq3 += __shfl_xor_sync(FULLM, sq3, o);
        sfl += __shfl_xor_sync(FULLM, sfl, o);
        sll += __shfl_xor_sync(FULLM, sll, o);
    }
    if (lane == 0) {
        float* p2 = &sRed[w * 6];
        p2[0]=sq0; p2[1]=sq1; p2[2]=sq2; p2[3]=sq3; p2[4]=sfl; p2[5]=sll;
    }
    __syncthreads();
    if (tid == 0) {
        float q0=0,q1=0,q2=0,q3=0,FLs=0,LLs=0;
        for (int j = 0; j < 8; j++) {
            q0 += sRed[j*6];   q1 += sRed[j*6+1]; q2 += sRed[j*6+2];
            q3 += sRed[j*6+3]; FLs += sRed[j*6+4]; LLs += sRed[j*6+5];
        }
        float kf = (float)k;
        float lb0 = PR[2], lb1 = PR[3], lb2 = PR[4], lb3 = PR[5];
        float dn0 = fmaxf(sqrtf(q0 + lb0*lb0), 1e-12f);
        float dn1 = fmaxf(sqrtf(q1 + lb1*lb1), 1e-12f);
        float dn2 = fmaxf(sqrtf(q2 + lb2*lb2), 1e-12f);
        float dn3 = fmaxf(sqrtf(q3 + lb3*lb3), 1e-12f);
        sB[1] = 1.0f/dn0; sB[2] = 1.0f/dn1; sB[3] = 1.0f/dn2; sB[4] = 1.0f/dn3;
        sB[5] = lb0/dn0;  sB[6] = lb1/dn1;  sB[7] = lb2/dn2;  sB[8] = lb3/dn3;
        sB[9]  = FLs / kf;
        sB[10] = LLs / kf;
    }
    __syncthreads();

    // pass B: smooth-L1 over selected rows using finalized column norms
    const float i0v = sB[1], i1v = sB[2], i2v = sB[3], i3v = sB[4];
    const float b0v = sB[5], b1v = sB[6], b2v = sB[7], b3v = sB[8];
    float ssl = 0.0f;
    #pragma unroll
    for (int rr = 0; rr < 4; rr++) {
        if (!(selMask & (1 << rr))) continue;
        const float* R = F + (tid + rr * 256) * 78;
        float2 v23 = *reinterpret_cast<const float2*>(R + 2);
        float2 v45 = *reinterpret_cast<const float2*>(R + 4);
        float h = 0.0f, d, ad;
        d = v23.x * i0v - b0v; ad = fabsf(d); h += (ad < 1.0f) ? 0.5f*d*d : ad - 0.5f;
        d = v23.y * i1v - b1v; ad = fabsf(d); h += (ad < 1.0f) ? 0.5f*d*d : ad - 0.5f;
        d = v45.x * i2v - b2v; ad = fabsf(d); h += (ad < 1.0f) ? 0.5f*d*d : ad - 0.5f;
        d = v45.y * i3v - b3v; ad = fabsf(d); h += (ad < 1.0f) ? 0.5f*d*d : ad - 0.5f;
        ssl += 0.25f * h;
    }
    for (int o = 16; o; o >>= 1) ssl += __shfl_xor_sync(FULLM, ssl, o);
    if (lane == 0) sRed[w] = ssl;
    __syncthreads();
    if (tid == 0) {
        float SSL = sRed[0]+sRed[1]+sRed[2]+sRed[3]
                  + sRed[4]+sRed[5]+sRed[6]+sRed[7];
        g_res[bid*3 + 0] = SSL / (float)k;
        g_res[bid*3 + 1] = sB[10];
        g_res[bid*3 + 2] = sB[9];
    }
    __syncthreads();

    // ---- folded final reduction: last block to finish combines everything ---
    __threadfence();
    if (tid == 0) {
        unsigned t = atomicAdd(&g_done, 1u);
        sLast = (t == (unsigned)(gridDim.x - 1));
    }
    __syncthreads();
    if (!sLast) return;
    __threadfence();

    float a = 0.0f, bb = 0.0f, cc = 0.0f;
    for (int i = tid; i < 1024; i += 256) {
        a  += g_res[i*3];
        bb += g_res[i*3+1];
        cc += g_res[i*3+2];
    }
    for (int o = 16; o; o >>= 1) {
        a  += __shfl_xor_sync(FULLM, a,  o);
        bb += __shfl_xor_sync(FULLM, bb, o);
        cc += __shfl_xor_sync(FULLM, cc, o);
    }
    if (lane == 0) { sRed[w] = a; sRed[w+16] = bb; sRed[w+32] = cc; }
    __syncthreads();
    if (tid == 0) {
        float A=0,B=0,C=0;
        for (int j = 0; j < 8; j++) { A += sRed[j]; B += sRed[j+16]; C += sRed[j+32]; }
        float sl = A * (1.0f/1024.0f);
        float ll = B * (1.0f/1024.0f);
        float fl = C * (1.0f/1024.0f);
        float loss = (sl > 0.0f ? 0.5f*sl : 0.0f)
                   + (ll > 0.0f ? 2.0f*ll : 0.0f)
                   + (fl > 0.0f ? 2.0f*fl : 0.0f);
        out[0] = loss;
        g_done = 0;                      // reset for next graph replay
    }
}

extern "C" void kernel_launch(void* const* d_in, const int* in_sizes, int n_in,
                              void* d_out, int out_size)
{
    const float* outp = (const float*)d_in[0];
    const float* lab  = (const float*)d_in[1];
    if (n_in >= 2 && in_sizes[0] == 64*16*78) {   // defensive: metadata order
        outp = (const float*)d_in[1];
        lab  = (const float*)d_in[0];
    }
    k_stats<<<dim3(64, 8, 2), 256>>>(outp, lab);
    k_sel  <<<1024, 256>>>(outp, lab, (float*)d_out);
}

// round 16
// speedup vs baseline: 1.0539x; 1.0539x over previous
#include <cuda_runtime.h>
#include <math.h>

#define FULLM 0xffffffffu

// Static scratch (no allocations)
__device__ float2 g_PL[1024000];     // [bid=b*16+p][row] -> {Pv=(dis*xy*th)^2 raw, l1}
__device__ float4 g_psum[8192];      // [bid][tile] -> {sum d2, sum dxy2, sum t2, sum liou}
__device__ float4 g_v01e[64000];     // [b][row] -> {v0, v1, exp(v0), exp(v1)}
__device__ float  g_Zp[64][8][2];    // partial sums of exp(v0), exp(v1)
__device__ float  g_res[3072];       // [1024][3]
__device__ unsigned g_done = 0;      // completion counter (reset each replay)

// ---------------------------------------------------------------------------
// Kernel 1: per-row stats vs priors + per-tile prior sums.
// blockDim 256 = 128 rows x 2 prior-groups (8 priors each). grid (64, 8 tiles).
// L1 inner loop uses packed f32x2 adds with negated priors; abs via 64-bit AND.
// ---------------------------------------------------------------------------
__global__ __launch_bounds__(256) void k_stats(const float* __restrict__ OUT,
                                               const float* __restrict__ LAB)
{
    const int b = blockIdx.x, tile = blockIdx.y;
    const int tid = threadIdx.x;
    const int pg  = tid >> 7;          // 0: priors 0-7, 1: priors 8-15
    const int rl  = tid & 127;
    const int w = tid >> 5, lane = tid & 31;

    __shared__ __align__(16) float sNL1[16 * 72];  // negated prior cols 6..77
    __shared__ float sXY[16][4];                   // negated prior cols 3,4,5
    __shared__ float sE[8];
    __shared__ float sW[8][32];                    // per-warp partials [warp][j*4+c]

    for (int j = tid; j < 1248; j += 256) {
        int p = j / 78, c = j - p * 78;
        float v = LAB[(long long)b * 1248 + j];
        if (c >= 6)               sNL1[p * 72 + (c - 6)] = -v;
        else if (c >= 3)          sXY[p][c - 3] = -v;
    }
    __syncthreads();

    const int row = tile * 125 + rl;
    const bool act = (rl < 125);
    float e0 = 0.0f, e1 = 0.0f;
    unsigned long long acc[8];
    float2 v23, v45;

    const float* R = OUT + (long long)b * 78000 + row * 78;

    if (act) {
        float2 v01 = *reinterpret_cast<const float2*>(R);
        v23 = *reinterpret_cast<const float2*>(R + 2);
        v45 = *reinterpret_cast<const float2*>(R + 4);
        if (pg == 0) {
            e0 = expf(v01.x);
            e1 = expf(v01.y);
            g_v01e[b * 1000 + row] = make_float4(v01.x, v01.y, e0, e1);
        }
        #pragma unroll
        for (int j = 0; j < 8; j++) acc[j] = 0ULL;

        const float* PB = sNL1 + pg * 8 * 72;
        #pragma unroll 3
        for (int cp = 0; cp < 18; cp++) {
            const unsigned long long vA =
                *reinterpret_cast<const unsigned long long*>(R + 6 + 4 * cp);
            const unsigned long long vB =
                *reinterpret_cast<const unsigned long long*>(R + 8 + 4 * cp);
            #pragma unroll
            for (int j = 0; j < 8; j++) {
                const ulonglong2 pp =
                    *reinterpret_cast<const ulonglong2*>(PB + j * 72 + 4 * cp);
                unsigned long long d;
                asm("add.rn.f32x2 %0, %1, %2;" : "=l"(d) : "l"(vA), "l"(pp.x));
                d &= 0x7FFFFFFF7FFFFFFFULL;
                asm("add.rn.f32x2 %0, %0, %1;" : "+l"(acc[j]) : "l"(d));
                asm("add.rn.f32x2 %0, %1, %2;" : "=l"(d) : "l"(vB), "l"(pp.y));
                d &= 0x7FFFFFFF7FFFFFFFULL;
                asm("add.rn.f32x2 %0, %0, %1;" : "+l"(acc[j]) : "l"(d));
            }
        }
    }

    // per-prior: compute {Pv, l1}, accumulate tile sums {d2, dxy2, t2, liou}
    #pragma unroll
    for (int j = 0; j < 8; j++) {
        float d2 = 0.0f, dxy2 = 0.0f, t2 = 0.0f, li = 0.0f;
        if (act) {
            const int p = pg * 8 + j;
            float dx = v23.y + sXY[p][0];
            float dy = v45.x + sXY[p][1];
            dxy2 = dx * dx + dy * dy;
            float th = v45.y + sXY[p][2];
            t2 = th * th;
            unsigned lo = (unsigned)acc[j];
            unsigned hi = (unsigned)(acc[j] >> 32);
            float l1 = __uint_as_float(lo) + __uint_as_float(hi);
            float dis = l1 * (1.0f / 72.0f);
            d2 = dis * dis;
            // liou = 2*l1/(2160+l1): poly approx of 1/(1+u), u = l1/2160 (k-sum only)
            float u = l1 * (1.0f / 2160.0f);
            li = 2.0f * l1 * (1.0f / 2160.0f) * (1.0f - u * (1.0f - u * (1.0f - u)));
            g_PL[(long long)(b * 16 + p) * 1000 + row] =
                make_float2(d2 * dxy2 * t2, l1);
        }
        for (int o = 16; o; o >>= 1) {
            d2   += __shfl_xor_sync(FULLM, d2,   o);
            dxy2 += __shfl_xor_sync(FULLM, dxy2, o);
            t2   += __shfl_xor_sync(FULLM, t2,   o);
            li   += __shfl_xor_sync(FULLM, li,   o);
        }
        if (lane == 0) {
            sW[w][j*4+0] = d2; sW[w][j*4+1] = dxy2;
            sW[w][j*4+2] = t2; sW[w][j*4+3] = li;
        }
    }

    if (pg == 0) {
        for (int o = 16; o; o >>= 1) {
            e0 += __shfl_xor_sync(FULLM, e0, o);
            e1 += __shfl_xor_sync(FULLM, e1, o);
        }
        if (lane == 0) { sE[w] = e0; sE[w + 4] = e1; }
    }
    __syncthreads();

    if (tid < 64) {
        int p = tid >> 2, c = tid & 3, j = p & 7;
        int wb = (p >= 8) ? 4 : 0;
        float s = sW[wb][j*4+c] + sW[wb+1][j*4+c] + sW[wb+2][j*4+c] + sW[wb+3][j*4+c];
        ((float*)g_psum)[(((b * 16 + p) * 8) + tile) * 4 + c] = s;
    }
    if (tid == 0) {
        g_Zp[b][tile][0] = sE[0] + sE[1] + sE[2] + sE[3];
        g_Zp[b][tile][1] = sE[4] + sE[5] + sE[6] + sE[7];
    }
}

// ---------------------------------------------------------------------------
// Kernel 2 (identical to the 35.3us R12 version): per-(batch,lane) cost keys,
// 4-pass radix top-k set selection, masked tails, folded final reduce.
// grid = 1024 blocks, 128 threads.
// ---------------------------------------------------------------------------
__global__ __launch_bounds__(128) void k_sel(const float* __restrict__ OUT,
                                             const float* __restrict__ LAB,
                                             float* __restrict__ out)
{
    const int bid = blockIdx.x;
    const int b = bid >> 4;
    const float* F  = OUT + (long long)b * 78000;
    const float* PR = LAB + (long long)bid * 78;

    __shared__ unsigned sKey[1000];
    __shared__ int      sHist[2][256];
    __shared__ float    sRed[32];
    __shared__ float    sB[12];        // 0:cscale 1:lnZ0 2:iZ0 3:lnZ1 4:iZ1 5..: norms
    __shared__ int      sKk;
    __shared__ unsigned sPfxS;
    __shared__ int      sKkS, sCLS, sCES;
    __shared__ bool     sLast;

    const int tid = threadIdx.x, w = tid >> 5, lane = tid & 31;

    // phase 0: warp-parallel preliminaries (Z, cscale, k, hist zero) — 1 barrier
    if (w == 0) {
        float z = 0.0f;
        if (lane < 8)       z = g_Zp[b][lane][0];
        else if (lane < 16) z = g_Zp[b][lane - 8][1];
        z += __shfl_xor_sync(FULLM, z, 4);
        z += __shfl_xor_sync(FULLM, z, 2);
        z += __shfl_xor_sync(FULLM, z, 1);
        if (lane == 0) { sB[1] = logf(z); sB[2] = 1.0f / z; }
        if (lane == 8) { sB[3] = logf(z); sB[4] = 1.0f / z; }
    } else if (w == 1) {
        float4 p4 = make_float4(0.0f, 0.0f, 0.0f, 0.0f);
        if (lane < 8) p4 = g_psum[bid * 8 + lane];
        #pragma unroll
        for (int o = 4; o; o >>= 1) {
            p4.x += __shfl_xor_sync(FULLM, p4.x, o);
            p4.y += __shfl_xor_sync(FULLM, p4.y, o);
            p4.z += __shfl_xor_sync(FULLM, p4.z, o);
            p4.w += __shfl_xor_sync(FULLM, p4.w, o);
        }
        if (lane == 0) {
            float nd = fmaxf(sqrtf(p4.x), 1e-12f);
            float nx = fmaxf(sqrtf(p4.y), 1e-12f);
            float nt = fmaxf(sqrtf(p4.z), 1e-12f);
            float den = nd * nx * nt;
            sB[0] = 3.0f / (den * den);        // W_SIM / (Nd*Nxy*Nth)^2
            int k = (int)p4.w;
            if (k < 1) k = 1;
            if (k > 64) k = 64;
            sKk = k;
            sPfxS = 0u; sCLS = 0; sKkS = k; sCES = 0;
        }
    } else {
        for (int j = tid - 64; j < 512; j += 64) ((int*)sHist)[j] = 0;
    }
    __syncthreads();

    const float cscale = sB[0];
    const float lnZ0 = sB[1], iZ0 = sB[2], lnZ1 = sB[3], iZ1 = sB[4];
    const int   k = sKk;
    const float pr0 = PR[0], pr1 = PR[1];
    const int nr = (tid < 104) ? 8 : 7;     // 104*8 + 24*7 = 1000

    // phase 1: compute final order-preserving keys directly
    unsigned kr[8];
    float l1r[8];
    #pragma unroll
    for (int rr = 0; rr < 8; rr++) {
        kr[rr] = 0xFFFFFFFFu; l1r[rr] = 0.0f;
        if (rr < nr) {
            int i = tid + rr * 128;
            float2 st = g_PL[(long long)bid * 1000 + i];
            float4 ve = g_v01e[b * 1000 + i];
            float s0 = ve.z * iZ0, s1 = ve.w * iZ1;
            float a0 = (1.0f - s0); a0 = a0 * a0 * (ve.x - lnZ0);
            float a1 = (1.0f - s1); a1 = a1 * a1 * (ve.y - lnZ1);
            float cost = cscale * st.x + a0 * pr0 + a1 * pr1;   // W_CLS = 1
            unsigned u = __float_as_uint(cost);
            u = (u & 0x80000000u) ? ~u : (u | 0x80000000u);
            kr[rr] = u;
            sKey[i] = u;
            l1r[rr] = st.y;
        }
    }

    // 4-pass radix select (MSB first): exact k-th smallest key + CL/CE
    #pragma unroll
    for (int p = 0; p < 4; p++) {
        const int shift = 24 - 8 * p;
        const int buf = p & 1;
        const unsigned pfx = sPfxS;
        #pragma unroll
        for (int rr = 0; rr < 8; rr++) {
            if (rr < nr) {
                bool match = (p == 0) || (((kr[rr] ^ pfx) >> (shift + 8)) == 0u);
                if (match) atomicAdd(&sHist[buf][(kr[rr] >> shift) & 255u], 1);
            }
        }
        __syncthreads();
        if (w == 0) {
            int hv[8]; int local = 0;
            #pragma unroll
            for (int j = 0; j < 8; j++) { hv[j] = sHist[buf][lane * 8 + j]; local += hv[j]; }
            int inc = local;
            #pragma unroll
            for (int o = 1; o < 32; o <<= 1) {
                int t = __shfl_up_sync(FULLM, inc, o);
                if (lane >= o) inc += t;
            }
            const int cumb = inc - local;
            const int kk = sKkS;
            unsigned ball = __ballot_sync(FULLM, inc >= kk);
            int sel_lane = __ffs(ball) - 1;
            if (lane == sel_lane) {
                int run = cumb;
                #pragma unroll
                for (int j = 0; j < 8; j++) {
                    int h = hv[j];
                    if (run + h >= kk) {
                        sPfxS = pfx | ((unsigned)(lane * 8 + j) << shift);
                        sKkS  = kk - run;
                        sCLS += run;
                        sCES  = h;
                        break;
                    }
                    run += h;
                }
            }
        } else {
            for (int j = tid - 32; j < 256; j += 96) sHist[buf ^ 1][j] = 0;
        }
        __syncthreads();
    }
    const unsigned Tkey = sPfxS;
    const int CL = sCLS, CE = sCES;
    const int  m    = k - CL;
    const bool easy = (CE == m);

    // pass A: select + accumulate col sums, focal, liou over selected rows
    const int tgt = (pr0 >= pr1) ? 0 : 1;
    float sq0=0, sq1=0, sq2=0, sq3=0, sfl=0, sll=0;
    int selMask = 0;
    #pragma unroll
    for (int rr = 0; rr < 8; rr++) {
        if (rr >= nr) continue;
        int i = tid + rr * 128;
        bool s;
        if (kr[rr] < Tkey) s = true;
        else if (kr[rr] == Tkey) {
            if (easy) s = true;
            else {
                int rank = 0;
                for (int j = 0; j < i; j++) rank += (sKey[j] == Tkey) ? 1 : 0;
                s = (rank < m);
            }
        } else s = false;
        if (s) {
            selMask |= (1 << rr);
            const float* R = F + i * 78;
            float2 v23 = *reinterpret_cast<const float2*>(R + 2);
            float2 v45 = *reinterpret_cast<const float2*>(R + 4);
            sq0 += v23.x * v23.x;  sq1 += v23.y * v23.y;
            sq2 += v45.x * v45.x;  sq3 += v45.y * v45.y;
            float4 ve = g_v01e[b * 1000 + i];
            float at = (tgt == 0) ? ve.x : ve.y;
            float ao = (tgt == 0) ? ve.y : ve.x;
            float e  = expf(ao - at);
            float lp = -log1pf(e);
            float pt = expf(lp);
            float om = 1.0f - pt;
            sfl += -om * om * lp;
            float l1 = l1r[rr];
            sll += 1.0f - __fdividef(2160.0f - l1, 2160.0f + l1 + 1e-9f);
        }
    }
    for (int o = 16; o; o >>= 1) {
        sq0 += __shfl_xor_sync(FULLM, sq0, o);
        sq1 += __shfl_xor_sync(FULLM, sq1, o);
        sq2 += __shfl_xor_sync(FULLM, sq2, o);
        sq3 += __shfl_xor_sync(FULLM, sq3, o);
        sfl += __shfl_xor_sync(FULLM, sfl, o);
        sll += __shfl_xor_sync(FULLM, sll, o);
    }
    if (lane == 0) {
        float* p2 = &sRed[w * 6];
        p2[0]=sq0; p2[1]=sq1; p2[2]=sq2; p2[3]=sq3; p2[4]=sfl; p2[5]=sll;
    }
    __syncthreads();
    if (tid == 0) {
        float q0=0,q1=0,q2=0,q3=0,FLs=0,LLs=0;
        for (int j = 0; j < 4; j++) {
            q0 += sRed[j*6];   q1 += sRed[j*6+1]; q2 += sRed[j*6+2];
            q3 += sRed[j*6+3]; FLs += sRed[j*6+4]; LLs += sRed[j*6+5];
        }
        float kf = (float)k;
        float lb0 = PR[2], lb1 = PR[3], lb2 = PR[4], lb3 = PR[5];
        float dn0 = fmaxf(sqrtf(q0 + lb0*lb0), 1e-12f);
        float dn1 = fmaxf(sqrtf(q1 + lb1*lb1), 1e-12f);
        float dn2 = fmaxf(sqrtf(q2 + lb2*lb2), 1e-12f);
        float dn3 = fmaxf(sqrtf(q3 + lb3*lb3), 1e-12f);
        sB[1] = 1.0f/dn0; sB[2] = 1.0f/dn1; sB[3] = 1.0f/dn2; sB[4] = 1.0f/dn3;
        sB[5] = lb0/dn0;  sB[6] = lb1/dn1;  sB[7] = lb2/dn2;  sB[8] = lb3/dn3;
        sB[9]  = FLs / kf;
        sB[10] = LLs / kf;
    }
    __syncthreads();

    // pass B: smooth-L1 over selected rows using finalized column norms
    const float i0v = sB[1], i1v = sB[2], i2v = sB[3], i3v = sB[4];
    const float b0v = sB[5], b1v = sB[6], b2v = sB[7], b3v = sB[8];
    float ssl = 0.0f;
    #pragma unroll
    for (int rr = 0; rr < 8; rr++) {
        if (!(selMask & (1 << rr))) continue;
        const float* R = F + (tid + rr * 128) * 78;
        float2 v23 = *reinterpret_cast<const float2*>(R + 2);
        float2 v45 = *reinterpret_cast<const float2*>(R + 4);
        float h = 0.0f, d, ad;
        d = v23.x * i0v - b0v; ad = fabsf(d); h += (ad < 1.0f) ? 0.5f*d*d : ad - 0.5f;
        d = v23.y * i1v - b1v; ad = fabsf(d); h += (ad < 1.0f) ? 0.5f*d*d : ad - 0.5f;
        d = v45.x * i2v - b2v; ad = fabsf(d); h += (ad < 1.0f) ? 0.5f*d*d : ad - 0.5f;
        d = v45.y * i3v - b3v; ad = fabsf(d); h += (ad < 1.0f) ? 0.5f*d*d : ad - 0.5f;
        ssl += 0.25f * h;
    }
    for (int o = 16; o; o >>= 1) ssl += __shfl_xor_sync(FULLM, ssl, o);
    if (lane == 0) sRed[w] = ssl;
    __syncthreads();
    if (tid == 0) {
        float SSL = sRed[0] + sRed[1] + sRed[2] + sRed[3];
        g_res[bid*3 + 0] = SSL / (float)k;
        g_res[bid*3 + 1] = sB[10];
        g_res[bid*3 + 2] = sB[9];
    }
    __syncthreads();

    // ---- folded final reduction: last block to finish combines everything ---
    __threadfence();
    if (tid == 0) {
        unsigned t = atomicAdd(&g_done, 1u);
        sLast = (t == (unsigned)(gridDim.x - 1));
    }
    __syncthreads();
    if (!sLast) return;
    __threadfence();

    float a = 0.0f, bb = 0.0f, cc = 0.0f;
    for (int i = tid; i < 1024; i += 128) {
        a  += g_res[i*3];
        bb += g_res[i*3+1];
        cc += g_res[i*3+2];
    }
    for (int o = 16; o; o >>= 1) {
        a  += __shfl_xor_sync(FULLM, a,  o);
        bb += __shfl_xor_sync(FULLM, bb, o);
        cc += __shfl_xor_sync(FULLM, cc, o);
    }
    if (lane == 0) { sRed[w] = a; sRed[w+8] = bb; sRed[w+16] = cc; }
    __syncthreads();
    if (tid == 0) {
        float A = sRed[0]+sRed[1]+sRed[2]+sRed[3];
        float B = sRed[8]+sRed[9]+sRed[10]+sRed[11];
        float C = sRed[16]+sRed[17]+sRed[18]+sRed[19];
        float sl = A * (1.0f/1024.0f);
        float ll = B * (1.0f/1024.0f);
        float fl = C * (1.0f/1024.0f);
        float loss = (sl > 0.0f ? 0.5f*sl : 0.0f)
                   + (ll > 0.0f ? 2.0f*ll : 0.0f)
                   + (fl > 0.0f ? 2.0f*fl : 0.0f);
        out[0] = loss;
        g_done = 0;                      // reset for next graph replay
    }
}

extern "C" void kernel_launch(void* const* d_in, const int* in_sizes, int n_in,
                              void* d_out, int out_size)
{
    const float* outp = (const float*)d_in[0];
    const float* lab  = (const float*)d_in[1];
    if (n_in >= 2 && in_sizes[0] == 64*16*78) {   // defensive: metadata order
        outp = (const float*)d_in[1];
        lab  = (const float*)d_in[0];
    }
    k_stats<<<dim3(64, 8), 256>>>(outp, lab);
    k_sel  <<<1024, 128>>>(outp, lab, (float*)d_out);
}

// round 17
// speedup vs baseline: 1.1070x; 1.0504x over previous
#include <cuda_runtime.h>
#include <math.h>

#define FULLM 0xffffffffu

// Static scratch (no allocations)
__device__ float2 g_PL[1024000];     // [bid=b*16+p][row] -> {Pv=(dis*xy*th)^2 raw, l1}
__device__ float4 g_psum[8192];      // [bid][tile] -> {sum d2, sum dxy2, sum t2, sum liou}
__device__ float4 g_v01e[64000];     // [b][row] -> {v0, v1, exp(v0), exp(v1)}
__device__ float  g_Zp[64][8][2];    // partial sums of exp(v0), exp(v1)
__device__ float  g_res[3072];       // [1024][3]
__device__ unsigned g_done = 0;      // completion counter (reset each replay)

// ---------------------------------------------------------------------------
// Kernel 1 (R12 version): per-row stats vs priors + per-tile prior sums.
// blockDim 256 = 128 rows x 2 prior-groups. grid (64 batches, 8 tiles of 125).
// ---------------------------------------------------------------------------
__global__ __launch_bounds__(256) void k_stats(const float* __restrict__ OUT,
                                               const float* __restrict__ LAB)
{
    const int b = blockIdx.x, tile = blockIdx.y;
    const int tid = threadIdx.x;
    const int pg  = tid >> 7;          // 0: priors 0-7, 1: priors 8-15
    const int rl  = tid & 127;
    const int w = tid >> 5, lane = tid & 31;

    __shared__ float sPr[1248];        // 16 priors x 78
    __shared__ float sE[8];
    __shared__ float sW[8][32];        // per-warp partials [warp][j*4+c]
    for (int j = tid; j < 1248; j += 256) sPr[j] = LAB[(long long)b * 1248 + j];
    __syncthreads();

    const int row = tile * 125 + rl;
    const bool act = (rl < 125);
    float e0 = 0.0f, e1 = 0.0f;
    float acc[8];
    float2 v23, v45;

    const float* R = OUT + (long long)b * 78000 + row * 78;
    const float* P0 = sPr + pg * 8 * 78;

    if (act) {
        float2 v01 = *reinterpret_cast<const float2*>(R);
        v23 = *reinterpret_cast<const float2*>(R + 2);
        v45 = *reinterpret_cast<const float2*>(R + 4);
        if (pg == 0) {
            e0 = expf(v01.x);
            e1 = expf(v01.y);
            g_v01e[b * 1000 + row] = make_float4(v01.x, v01.y, e0, e1);
        }
        #pragma unroll
        for (int j = 0; j < 8; j++) acc[j] = 0.0f;
        #pragma unroll 4
        for (int c = 6; c < 78; c += 2) {
            float2 v = *reinterpret_cast<const float2*>(R + c);
            #pragma unroll
            for (int j = 0; j < 8; j++) {
                float2 pv = *reinterpret_cast<const float2*>(P0 + j * 78 + c);
                acc[j] += fabsf(v.x - pv.x) + fabsf(v.y - pv.y);
            }
        }
    }

    #pragma unroll
    for (int j = 0; j < 8; j++) {
        float d2 = 0.0f, dxy2 = 0.0f, t2 = 0.0f, li = 0.0f;
        if (act) {
            const float* Pj = P0 + j * 78;
            float dx = v23.y - Pj[3];
            float dy = v45.x - Pj[4];
            dxy2 = dx * dx + dy * dy;
            float th = v45.y - Pj[5];
            t2 = th * th;
            float l1 = acc[j];
            float dis = l1 * (1.0f / 72.0f);
            d2 = dis * dis;
            float u = l1 * (1.0f / 2160.0f);
            li = 2.0f * l1 * (1.0f / 2160.0f) * (1.0f - u * (1.0f - u * (1.0f - u)));
            g_PL[(long long)(b * 16 + pg * 8 + j) * 1000 + row] =
                make_float2(d2 * dxy2 * t2, l1);
        }
        for (int o = 16; o; o >>= 1) {
            d2   += __shfl_xor_sync(FULLM, d2,   o);
            dxy2 += __shfl_xor_sync(FULLM, dxy2, o);
            t2   += __shfl_xor_sync(FULLM, t2,   o);
            li   += __shfl_xor_sync(FULLM, li,   o);
        }
        if (lane == 0) {
            sW[w][j*4+0] = d2; sW[w][j*4+1] = dxy2;
            sW[w][j*4+2] = t2; sW[w][j*4+3] = li;
        }
    }

    if (pg == 0) {
        for (int o = 16; o; o >>= 1) {
            e0 += __shfl_xor_sync(FULLM, e0, o);
            e1 += __shfl_xor_sync(FULLM, e1, o);
        }
        if (lane == 0) { sE[w] = e0; sE[w + 4] = e1; }
    }
    __syncthreads();

    if (tid < 64) {
        int p = tid >> 2, c = tid & 3, j = p & 7;
        int wb = (p >= 8) ? 4 : 0;
        float s = sW[wb][j*4+c] + sW[wb+1][j*4+c] + sW[wb+2][j*4+c] + sW[wb+3][j*4+c];
        ((float*)g_psum)[(((b * 16 + p) * 8) + tile) * 4 + c] = s;
    }
    if (tid == 0) {
        g_Zp[b][tile][0] = sE[0] + sE[1] + sE[2] + sE[3];
        g_Zp[b][tile][1] = sE[4] + sE[5] + sE[6] + sE[7];
    }
}

// ---------------------------------------------------------------------------
// Kernel 2: MERGED selection — 4 priors per block, shared phase-0 / a01 /
// barriers / radix scans. grid = 256 blocks (b = blk/4, priors 4*(blk%4)..+3),
// 512 threads = 4 prior-groups x 128.
// ---------------------------------------------------------------------------
__global__ __launch_bounds__(512, 2) void k_sel(const float* __restrict__ OUT,
                                                const float* __restrict__ LAB,
                                                float* __restrict__ out)
{
    const int blk = blockIdx.x;
    const int b  = blk >> 2;
    const int p0 = (blk & 3) * 4;
    const float* F = OUT + (long long)b * 78000;

    __shared__ unsigned sKeyA[4][1000];
    __shared__ float4   sA01[1000];        // {a0, a1, v0, v1} per row
    __shared__ int      sHist[4][2][256];
    __shared__ float    sZ[4];             // lnZ0, iZ0, lnZ1, iZ1
    __shared__ float    sCsc[4];
    __shared__ int      sKk[4];
    __shared__ unsigned sPfx[4];
    __shared__ int      sKkS[4], sCLS[4], sCES[4];
    __shared__ float    sRedA[4][4][6];
    __shared__ float    sRedB[4][4];
    __shared__ float    sNorm[4][8];
    __shared__ float    sFLk[4], sLLk[4];
    __shared__ float    sFin[48];
    __shared__ bool     sLast;

    const int tid = threadIdx.x, w = tid >> 5, lane = tid & 31;
    const int q = tid >> 7;                // prior-group 0..3
    const int t = tid & 127;               // thread within group
    const int wg = (tid >> 5) & 3;         // warp within group

    // ---- phase 0: Z, per-prior cscale/k, hist zero (disjoint warps) --------
    if (w == 0) {
        float z = 0.0f;
        if (lane < 8)       z = g_Zp[b][lane][0];
        else if (lane < 16) z = g_Zp[b][lane - 8][1];
        z += __shfl_xor_sync(FULLM, z, 4);
        z += __shfl_xor_sync(FULLM, z, 2);
        z += __shfl_xor_sync(FULLM, z, 1);
        if (lane == 0) { sZ[0] = logf(z); sZ[1] = 1.0f / z; }
        if (lane == 8) { sZ[2] = logf(z); sZ[3] = 1.0f / z; }
    } else if (w <= 4) {
        const int qq = w - 1;
        float4 p4 = make_float4(0.0f, 0.0f, 0.0f, 0.0f);
        if (lane < 8) p4 = g_psum[(b * 16 + p0 + qq) * 8 + lane];
        #pragma unroll
        for (int o = 4; o; o >>= 1) {
            p4.x += __shfl_xor_sync(FULLM, p4.x, o);
            p4.y += __shfl_xor_sync(FULLM, p4.y, o);
            p4.z += __shfl_xor_sync(FULLM, p4.z, o);
            p4.w += __shfl_xor_sync(FULLM, p4.w, o);
        }
        if (lane == 0) {
            float nd = fmaxf(sqrtf(p4.x), 1e-12f);
            float nx = fmaxf(sqrtf(p4.y), 1e-12f);
            float nt = fmaxf(sqrtf(p4.z), 1e-12f);
            float den = nd * nx * nt;
            sCsc[qq] = 3.0f / (den * den);      // W_SIM / (Nd*Nxy*Nth)^2
            int k = (int)p4.w;
            if (k < 1) k = 1;
            if (k > 64) k = 64;
            sKk[qq] = k;
            sPfx[qq] = 0u; sKkS[qq] = k; sCLS[qq] = 0; sCES[qq] = 0;
        }
    } else {
        int* H = &sHist[0][0][0];
        for (int j = tid - 160; j < 2048; j += 352) H[j] = 0;
    }
    __syncthreads();

    // ---- phase 0b: per-row focal ingredients, computed ONCE per row --------
    const float lnZ0 = sZ[0], iZ0 = sZ[1], lnZ1 = sZ[2], iZ1 = sZ[3];
    for (int r = tid; r < 1000; r += 512) {
        float4 ve = g_v01e[b * 1000 + r];
        float s0 = ve.z * iZ0, s1 = ve.w * iZ1;
        float a0 = (1.0f - s0); a0 = a0 * a0 * (ve.x - lnZ0);
        float a1 = (1.0f - s1); a1 = a1 * a1 * (ve.y - lnZ1);
        sA01[r] = make_float4(a0, a1, ve.x, ve.y);
    }
    __syncthreads();

    // ---- phase 1: keys for this prior-group --------------------------------
    const float* PRq = LAB + (long long)(b * 16 + p0 + q) * 78;
    const float pr0 = PRq[0], pr1 = PRq[1];
    const float cscale = sCsc[q];
    const int   k = sKk[q];
    const long long base = (long long)(b * 16 + p0 + q) * 1000;
    const int nr = (t < 104) ? 8 : 7;     // 104*8 + 24*7 = 1000

    unsigned kr[8];
    float l1r[8];
    #pragma unroll
    for (int rr = 0; rr < 8; rr++) {
        kr[rr] = 0xFFFFFFFFu; l1r[rr] = 0.0f;
        if (rr < nr) {
            int i = t + rr * 128;
            float2 st = g_PL[base + i];
            float4 A  = sA01[i];
            float cost = cscale * st.x + A.x * pr0 + A.y * pr1;   // W_CLS = 1
            unsigned u = __float_as_uint(cost);
            u = (u & 0x80000000u) ? ~u : (u | 0x80000000u);
            kr[rr] = u;
            sKeyA[q][i] = u;
            l1r[rr] = st.y;
        }
    }

    // ---- 4-pass radix select, 4 priors in parallel -------------------------
    #pragma unroll
    for (int p = 0; p < 4; p++) {
        const int shift = 24 - 8 * p;
        const int buf = p & 1;
        const unsigned pfx = sPfx[q];
        #pragma unroll
        for (int rr = 0; rr < 8; rr++) {
            if (rr < nr) {
                bool match = (p == 0) || (((kr[rr] ^ pfx) >> (shift + 8)) == 0u);
                if (match) atomicAdd(&sHist[q][buf][(kr[rr] >> shift) & 255u], 1);
            }
        }
        __syncthreads();
        if (w < 4) {
            const int q2 = w;
            int hv[8]; int local = 0;
            #pragma unroll
            for (int j = 0; j < 8; j++) { hv[j] = sHist[q2][buf][lane * 8 + j]; local += hv[j]; }
            int inc = local;
            #pragma unroll
            for (int o = 1; o < 32; o <<= 1) {
                int tt = __shfl_up_sync(FULLM, inc, o);
                if (lane >= o) inc += tt;
            }
            const int cumb = inc - local;
            const int kk = sKkS[q2];
            unsigned ball = __ballot_sync(FULLM, inc >= kk);
            int sel_lane = __ffs(ball) - 1;
            if (lane == sel_lane) {
                int run = cumb;
                const unsigned pfx2 = sPfx[q2];
                #pragma unroll
                for (int j = 0; j < 8; j++) {
                    int h = hv[j];
                    if (run + h >= kk) {
                        sPfx[q2] = pfx2 | ((unsigned)(lane * 8 + j) << shift);
                        sKkS[q2] = kk - run;
                        sCLS[q2] += run;
                        sCES[q2] = h;
                        break;
                    }
                    run += h;
                }
            }
        } else {
            // zero the other buffer (all 4 priors) for the next pass
            for (int j = tid - 128; j < 1024; j += 384)
                sHist[j >> 8][buf ^ 1][j & 255] = 0;
        }
        __syncthreads();
    }
    const unsigned Tkey = sPfx[q];
    const int CL = sCLS[q], CE = sCES[q];
    const int  m    = k - CL;
    const bool easy = (CE == m);

    // ---- pass A: select + accumulate col sums, focal, liou -----------------
    const int tgt = (pr0 >= pr1) ? 0 : 1;
    float sq0=0, sq1=0, sq2=0, sq3=0, sfl=0, sll=0;
    int selMask = 0;
    #pragma unroll
    for (int rr = 0; rr < 8; rr++) {
        if (rr >= nr) continue;
        int i = t + rr * 128;
        bool s;
        if (kr[rr] < Tkey) s = true;
        else if (kr[rr] == Tkey) {
            if (easy) s = true;
            else {
                int rank = 0;
                for (int j = 0; j < i; j++) rank += (sKeyA[q][j] == Tkey) ? 1 : 0;
                s = (rank < m);
            }
        } else s = false;
        if (s) {
            selMask |= (1 << rr);
            const float* R = F + i * 78;
            float2 v23 = *reinterpret_cast<const float2*>(R + 2);
            float2 v45 = *reinterpret_cast<const float2*>(R + 4);
            sq0 += v23.x * v23.x;  sq1 += v23.y * v23.y;
            sq2 += v45.x * v45.x;  sq3 += v45.y * v45.y;
            float4 A = sA01[i];
            float at = (tgt == 0) ? A.z : A.w;
            float ao = (tgt == 0) ? A.w : A.z;
            float e  = expf(ao - at);
            float lp = -log1pf(e);
            float pt = expf(lp);
            float om = 1.0f - pt;
            sfl += -om * om * lp;
            float l1 = l1r[rr];
            sll += 1.0f - __fdividef(2160.0f - l1, 2160.0f + l1 + 1e-9f);
        }
    }
    for (int o = 16; o; o >>= 1) {
        sq0 += __shfl_xor_sync(FULLM, sq0, o);
        sq1 += __shfl_xor_sync(FULLM, sq1, o);
        sq2 += __shfl_xor_sync(FULLM, sq2, o);
        sq3 += __shfl_xor_sync(FULLM, sq3, o);
        sfl += __shfl_xor_sync(FULLM, sfl, o);
        sll += __shfl_xor_sync(FULLM, sll, o);
    }
    if (lane == 0) {
        float* p2 = sRedA[q][wg];
        p2[0]=sq0; p2[1]=sq1; p2[2]=sq2; p2[3]=sq3; p2[4]=sfl; p2[5]=sll;
    }
    __syncthreads();
    if (t == 0) {
        float q0=0,q1=0,q2=0,q3=0,FLs=0,LLs=0;
        for (int j = 0; j < 4; j++) {
            q0 += sRedA[q][j][0]; q1 += sRedA[q][j][1]; q2 += sRedA[q][j][2];
            q3 += sRedA[q][j][3]; FLs += sRedA[q][j][4]; LLs += sRedA[q][j][5];
        }
        float kf = (float)k;
        float lb0 = PRq[2], lb1 = PRq[3], lb2 = PRq[4], lb3 = PRq[5];
        float dn0 = fmaxf(sqrtf(q0 + lb0*lb0), 1e-12f);
        float dn1 = fmaxf(sqrtf(q1 + lb1*lb1), 1e-12f);
        float dn2 = fmaxf(sqrtf(q2 + lb2*lb2), 1e-12f);
        float dn3 = fmaxf(sqrtf(q3 + lb3*lb3), 1e-12f);
        sNorm[q][0] = 1.0f/dn0; sNorm[q][1] = 1.0f/dn1;
        sNorm[q][2] = 1.0f/dn2; sNorm[q][3] = 1.0f/dn3;
        sNorm[q][4] = lb0/dn0;  sNorm[q][5] = lb1/dn1;
        sNorm[q][6] = lb2/dn2;  sNorm[q][7] = lb3/dn3;
        sFLk[q] = FLs / kf;
        sLLk[q] = LLs / kf;
    }
    __syncthreads();

    // ---- pass B: smooth-L1 over selected rows ------------------------------
    const float i0v = sNorm[q][0], i1v = sNorm[q][1], i2v = sNorm[q][2], i3v = sNorm[q][3];
    const float b0v = sNorm[q][4], b1v = sNorm[q][5], b2v = sNorm[q][6], b3v = sNorm[q][7];
    float ssl = 0.0f;
    #pragma unroll
    for (int rr = 0; rr < 8; rr++) {
        if (!(selMask & (1 << rr))) continue;
        const float* R = F + (t + rr * 128) * 78;
        float2 v23 = *reinterpret_cast<const float2*>(R + 2);
        float2 v45 = *reinterpret_cast<const float2*>(R + 4);
        float h = 0.0f, d, ad;
        d = v23.x * i0v - b0v; ad = fabsf(d); h += (ad < 1.0f) ? 0.5f*d*d : ad - 0.5f;
        d = v23.y * i1v - b1v; ad = fabsf(d); h += (ad < 1.0f) ? 0.5f*d*d : ad - 0.5f;
        d = v45.x * i2v - b2v; ad = fabsf(d); h += (ad < 1.0f) ? 0.5f*d*d : ad - 0.5f;
        d = v45.y * i3v - b3v; ad = fabsf(d); h += (ad < 1.0f) ? 0.5f*d*d : ad - 0.5f;
        ssl += 0.25f * h;
    }
    for (int o = 16; o; o >>= 1) ssl += __shfl_xor_sync(FULLM, ssl, o);
    if (lane == 0) sRedB[q][wg] = ssl;
    __syncthreads();
    if (t == 0) {
        float SSL = sRedB[q][0] + sRedB[q][1] + sRedB[q][2] + sRedB[q][3];
        int bid2 = b * 16 + p0 + q;
        g_res[bid2*3 + 0] = SSL / (float)k;
        g_res[bid2*3 + 1] = sLLk[q];
        g_res[bid2*3 + 2] = sFLk[q];
    }
    __syncthreads();

    // ---- folded final reduction: last block combines everything ------------
    __threadfence();
    if (tid == 0) {
        unsigned tt = atomicAdd(&g_done, 1u);
        sLast = (tt == (unsigned)(gridDim.x - 1));
    }
    __syncthreads();
    if (!sLast) return;
    __threadfence();

    float a = 0.0f, bb = 0.0f, cc = 0.0f;
    for (int i = tid; i < 1024; i += 512) {
        a  += g_res[i*3];
        bb += g_res[i*3+1];
        cc += g_res[i*3+2];
    }
    for (int o = 16; o; o >>= 1) {
        a  += __shfl_xor_sync(FULLM, a,  o);
        bb += __shfl_xor_sync(FULLM, bb, o);
        cc += __shfl_xor_sync(FULLM, cc, o);
    }
    if (lane == 0) { sFin[w] = a; sFin[w+16] = bb; sFin[w+32] = cc; }
    __syncthreads();
    if (tid == 0) {
        float A=0,B=0,C=0;
        for (int j = 0; j < 16; j++) { A += sFin[j]; B += sFin[j+16]; C += sFin[j+32]; }
        float sl = A * (1.0f/1024.0f);
        float ll = B * (1.0f/1024.0f);
        float fl = C * (1.0f/1024.0f);
        float loss = (sl > 0.0f ? 0.5f*sl : 0.0f)
                   + (ll > 0.0f ? 2.0f*ll : 0.0f)
                   + (fl > 0.0f ? 2.0f*fl : 0.0f);
        out[0] = loss;
        g_done = 0;                      // reset for next graph replay
    }
}

extern "C" void kernel_launch(void* const* d_in, const int* in_sizes, int n_in,
                              void* d_out, int out_size)
{
    const float* outp = (const float*)d_in[0];
    const float* lab  = (const float*)d_in[1];
    if (n_in >= 2 && in_sizes[0] == 64*16*78) {   // defensive: metadata order
        outp = (const float*)d_in[1];
        lab  = (const float*)d_in[0];
    }
    k_stats<<<dim3(64, 8), 256>>>(outp, lab);
    k_sel  <<<256, 512>>>(outp, lab, (float*)d_out);
}